// round 3
// baseline (speedup 1.0000x reference)
#include <cuda_runtime.h>

#define NN 50000
#define EE 800000
#define ET (EE + NN)          // edges + self loops
#define F12 448               // 7 heads * 64 ch
#define F3  32

// ---------------- scratch (static device globals; no allocation allowed) ----
__device__ __align__(128) float g_bufA[(size_t)NN * F12];  // GEMM output h (per-head feats)
__device__ __align__(128) float g_bufB[(size_t)NN * F12];  // aggregated node feats
__device__ __align__(128) float g_bufC[(size_t)NN * F3];   // layer-3 h
__device__ float g_as[NN * 7];
__device__ float g_ad[NN * 7];
__device__ int g_cnt[NN];
__device__ int g_off[NN + 1];
__device__ int g_cur[NN];
__device__ int g_esrc[ET];

// ---------------- CSR build ------------------------------------------------
__global__ void zero_cnt_kernel() {
    int i = blockIdx.x * blockDim.x + threadIdx.x;
    if (i < NN) g_cnt[i] = 0;
}

__global__ void hist_kernel(const int* __restrict__ ei) {
    int e = blockIdx.x * blockDim.x + threadIdx.x;
    if (e >= ET) return;
    int dst = (e < EE) ? ei[EE + e] : (e - EE);
    atomicAdd(&g_cnt[dst], 1);
}

__global__ void scan_kernel() {
    __shared__ int sh[1024];
    __shared__ int carry_s;
    int tid = threadIdx.x;
    if (tid == 0) carry_s = 0;
    __syncthreads();
    for (int base = 0; base < NN; base += 1024) {
        int i = base + tid;
        int v = (i < NN) ? g_cnt[i] : 0;
        sh[tid] = v;
        __syncthreads();
        for (int off = 1; off < 1024; off <<= 1) {
            int t = (tid >= off) ? sh[tid - off] : 0;
            __syncthreads();
            sh[tid] += t;
            __syncthreads();
        }
        int incl = sh[tid];
        int c = carry_s;
        if (i < NN) { g_off[i] = c + incl - v; g_cur[i] = c + incl - v; }
        __syncthreads();
        if (tid == 1023) carry_s = c + sh[1023];
        __syncthreads();
    }
    if (tid == 0) g_off[NN] = carry_s;
}

__global__ void scatter_kernel(const int* __restrict__ ei) {
    int e = blockIdx.x * blockDim.x + threadIdx.x;
    if (e >= ET) return;
    int src, dst;
    if (e < EE) { src = ei[e]; dst = ei[EE + e]; }
    else        { src = e - EE; dst = src; }
    int p = atomicAdd(&g_cur[dst], 1);
    g_esrc[p] = src;
}

// ---------------- SGEMM (fp32, register-blocked) ---------------------------
// C[M,N] = A[M,K] @ B[K,N].  K % BK == 0, N % BN == 0 (true for all 3 layers).
template<int BM, int BN, int BK, int TM, int TN>
__global__ void sgemm_kernel(const float* __restrict__ A, const float* __restrict__ B,
                             float* __restrict__ C, int M, int N, int K) {
    constexpr int THREADS = (BM / TM) * (BN / TN);
    __shared__ __align__(16) float As[BK][BM + 4];   // transposed A tile
    __shared__ __align__(16) float Bs[BK][BN];
    const int tid = threadIdx.x;
    const int bm = blockIdx.y * BM;
    const int bn = blockIdx.x * BN;
    constexpr int TX = BN / TN;
    const int tx = tid % TX;
    const int ty = tid / TX;

    float acc[TM][TN];
#pragma unroll
    for (int i = 0; i < TM; i++)
#pragma unroll
        for (int j = 0; j < TN; j++) acc[i][j] = 0.f;

    for (int k0 = 0; k0 < K; k0 += BK) {
        // load A tile (guard M edge), store transposed
#pragma unroll
        for (int r = 0; r < BM * BK / 4; r += THREADS) {
            int f = r + tid;
            int row = f / (BK / 4);
            int cg = f % (BK / 4);
            float4 v = make_float4(0.f, 0.f, 0.f, 0.f);
            if (bm + row < M)
                v = *reinterpret_cast<const float4*>(&A[(size_t)(bm + row) * K + k0 + cg * 4]);
            As[cg * 4 + 0][row] = v.x;
            As[cg * 4 + 1][row] = v.y;
            As[cg * 4 + 2][row] = v.z;
            As[cg * 4 + 3][row] = v.w;
        }
        // load B tile (exact)
#pragma unroll
        for (int r = 0; r < BK * BN / 4; r += THREADS) {
            int f = r + tid;
            int row = f / (BN / 4);
            int col = (f % (BN / 4)) * 4;
            *reinterpret_cast<float4*>(&Bs[row][col]) =
                *reinterpret_cast<const float4*>(&B[(size_t)(k0 + row) * N + bn + col]);
        }
        __syncthreads();
#pragma unroll
        for (int k = 0; k < BK; k++) {
            float ar[TM], br[TN];
#pragma unroll
            for (int i = 0; i < TM; i += 4) {
                float4 a = *reinterpret_cast<const float4*>(&As[k][ty * TM + i]);
                ar[i] = a.x; ar[i + 1] = a.y; ar[i + 2] = a.z; ar[i + 3] = a.w;
            }
#pragma unroll
            for (int j = 0; j < TN; j += 4) {
                float4 b = *reinterpret_cast<const float4*>(&Bs[k][tx * TN + j]);
                br[j] = b.x; br[j + 1] = b.y; br[j + 2] = b.z; br[j + 3] = b.w;
            }
#pragma unroll
            for (int i = 0; i < TM; i++)
#pragma unroll
                for (int j = 0; j < TN; j++) acc[i][j] += ar[i] * br[j];
        }
        __syncthreads();
    }
#pragma unroll
    for (int i = 0; i < TM; i++) {
        int row = bm + ty * TM + i;
        if (row < M) {
#pragma unroll
            for (int j = 0; j < TN; j += 4) {
                float4 v = make_float4(acc[i][j], acc[i][j + 1], acc[i][j + 2], acc[i][j + 3]);
                *reinterpret_cast<float4*>(&C[(size_t)row * N + bn + tx * TN + j]) = v;
            }
        }
    }
}

// ---------------- per-(node,head) attention coefficients -------------------
template<int C, int NH>
__global__ void alpha_kernel(const float* __restrict__ h, const float* __restrict__ a_src,
                             const float* __restrict__ a_dst,
                             float* __restrict__ as, float* __restrict__ ad) {
    int gw = (blockIdx.x * blockDim.x + threadIdx.x) >> 5;
    int lane = threadIdx.x & 31;
    if (gw >= NN * NH) return;
    int n = gw / NH, hh = gw % NH;
    const float* hp = h + (size_t)n * NH * C + hh * C;
    float s = 0.f, d = 0.f;
#pragma unroll
    for (int c = lane; c < C; c += 32) {
        float v = hp[c];
        s += v * a_src[hh * C + c];
        d += v * a_dst[hh * C + c];
    }
#pragma unroll
    for (int o = 16; o; o >>= 1) {
        s += __shfl_down_sync(0xffffffffu, s, o);
        d += __shfl_down_sync(0xffffffffu, d, o);
    }
    if (lane == 0) { as[gw] = s; ad[gw] = d; }
}

// ---------------- gather-side online-softmax aggregation -------------------
// one warp per (dst node, head); lanes own C/32 channels each
template<int C, int NH, bool RELU, bool LSM>
__global__ void agg_kernel(const float* __restrict__ h, const float* __restrict__ as,
                           const float* __restrict__ ad, const float* __restrict__ bias,
                           float* __restrict__ out) {
    int gw = (blockIdx.x * blockDim.x + threadIdx.x) >> 5;
    int lane = threadIdx.x & 31;
    if (gw >= NN * NH) return;
    int n = gw / NH, hh = gw % NH;
    int beg = g_off[n], end = g_off[n + 1];
    float adn = ad[gw];
    constexpr int CPL = C / 32;
    float acc[CPL];
#pragma unroll
    for (int j = 0; j < CPL; j++) acc[j] = 0.f;
    float m = -1e30f, dsum = 0.f;
    for (int i = beg; i < end; i++) {
        int s = g_esrc[i];
        float e = as[s * NH + hh] + adn;
        e = e > 0.f ? e : 0.2f * e;                 // leaky relu
        float mn = fmaxf(m, e);
        float sc = __expf(m - mn);
        float w  = __expf(e - mn);
        dsum = dsum * sc + w;
        const float* hp = h + (size_t)s * NH * C + hh * C;
#pragma unroll
        for (int j = 0; j < CPL; j++)
            acc[j] = acc[j] * sc + w * __ldg(&hp[lane + 32 * j]);
        m = mn;
    }
    float inv = 1.f / (dsum + 1e-16f);
    if (!LSM) {
#pragma unroll
        for (int j = 0; j < CPL; j++) {
            float r = acc[j] * inv + bias[hh * C + lane + 32 * j];
            if (RELU) r = fmaxf(r, 0.f);
            out[(size_t)n * NH * C + hh * C + lane + 32 * j] = r;
        }
    } else {
        // layer 3: NH=1, C=32, one channel per lane -> fused log_softmax
        float r = acc[0] * inv + bias[lane];
        float mx = r;
#pragma unroll
        for (int o = 16; o; o >>= 1) mx = fmaxf(mx, __shfl_xor_sync(0xffffffffu, mx, o));
        float ex = __expf(r - mx);
        float sm = ex;
#pragma unroll
        for (int o = 16; o; o >>= 1) sm += __shfl_xor_sync(0xffffffffu, sm, o);
        out[(size_t)n * 32 + lane] = r - mx - logf(sm);
    }
}

// ---------------- launch ---------------------------------------------------
extern "C" void kernel_launch(void* const* d_in, const int* in_sizes, int n_in,
                              void* d_out, int out_size) {
    const float* x   = (const float*)d_in[0];
    const int*   ei  = (const int*)d_in[1];
    const float* W1  = (const float*)d_in[2];
    const float* a1s = (const float*)d_in[3];
    const float* a1d = (const float*)d_in[4];
    const float* b1  = (const float*)d_in[5];
    const float* W2  = (const float*)d_in[6];
    const float* a2s = (const float*)d_in[7];
    const float* a2d = (const float*)d_in[8];
    const float* b2  = (const float*)d_in[9];
    const float* W3  = (const float*)d_in[10];
    const float* a3s = (const float*)d_in[11];
    const float* a3d = (const float*)d_in[12];
    const float* b3  = (const float*)d_in[13];
    float* out = (float*)d_out;

    float *bufA, *bufB, *bufC, *pas, *pad_;
    cudaGetSymbolAddress((void**)&bufA, g_bufA);
    cudaGetSymbolAddress((void**)&bufB, g_bufB);
    cudaGetSymbolAddress((void**)&bufC, g_bufC);
    cudaGetSymbolAddress((void**)&pas, g_as);
    cudaGetSymbolAddress((void**)&pad_, g_ad);

    // ---- CSR by destination (rebuilt every call; graph is an input) ----
    zero_cnt_kernel<<<(NN + 255) / 256, 256>>>();
    hist_kernel<<<(ET + 255) / 256, 256>>>(ei);
    scan_kernel<<<1, 1024>>>();
    scatter_kernel<<<(ET + 255) / 256, 256>>>(ei);

    const int wb12 = (NN * 7 * 32 + 255) / 256;   // blocks for 7-head warp kernels
    const int wb3  = (NN * 1 * 32 + 255) / 256;

    // ---- layer 1 ----
    sgemm_kernel<128, 64, 16, 8, 4><<<dim3(F12 / 64, (NN + 127) / 128), 256>>>(x, W1, bufA, NN, F12, 256);
    alpha_kernel<64, 7><<<wb12, 256>>>(bufA, a1s, a1d, pas, pad_);
    agg_kernel<64, 7, true, false><<<wb12, 256>>>(bufA, pas, pad_, b1, bufB);

    // ---- layer 2 ----
    sgemm_kernel<128, 64, 16, 8, 4><<<dim3(F12 / 64, (NN + 127) / 128), 256>>>(bufB, W2, bufA, NN, F12, F12);
    alpha_kernel<64, 7><<<wb12, 256>>>(bufA, a2s, a2d, pas, pad_);
    agg_kernel<64, 7, true, false><<<wb12, 256>>>(bufA, pas, pad_, b2, bufB);

    // ---- layer 3 (+ fused log_softmax) ----
    sgemm_kernel<128, 32, 16, 8, 4><<<dim3(1, (NN + 127) / 128), 128>>>(bufB, W3, bufC, NN, F3, F12);
    alpha_kernel<32, 1><<<wb3, 256>>>(bufC, a3s, a3d, pas, pad_);
    agg_kernel<32, 1, false, true><<<wb3, 256>>>(bufC, pas, pad_, b3, out);
}

// round 5
// speedup vs baseline: 1.4229x; 1.4229x over previous
#include <cuda_runtime.h>
#include <cuda_bf16.h>
#include <cstdint>

#define NN 50000
#define EE 800000
#define ET (EE + NN)          // edges + self loops
#define F12 448               // 7 heads * 64 ch
#define F3  32

// ---------------- scratch (static device globals; no allocation allowed) ----
__device__ __align__(128) float g_bufA[(size_t)NN * F12];  // GEMM output h
__device__ __align__(128) float g_bufB[(size_t)NN * F12];  // aggregated node feats
__device__ __align__(128) float g_bufC[(size_t)NN * F3];   // layer-3 h
__device__ float g_as[NN * 7];
__device__ float g_ad[NN * 7];
__device__ int g_cnt[NN];
__device__ int g_off[NN + 1];
__device__ int g_cur[NN];
__device__ int g_esrc[ET];
// transposed + bf16-split weights: WT[n*K + k] = W[k*N + n]
__device__ __align__(128) __nv_bfloat16 g_wt1h[448 * 256], g_wt1l[448 * 256];
__device__ __align__(128) __nv_bfloat16 g_wt2h[448 * 448], g_wt2l[448 * 448];
__device__ __align__(128) __nv_bfloat16 g_wt3h[32 * 448],  g_wt3l[32 * 448];

// ---------------- CSR build ------------------------------------------------
__global__ void zero_cnt_kernel() {
    int i = blockIdx.x * blockDim.x + threadIdx.x;
    if (i < NN) g_cnt[i] = 0;
}
__global__ void hist_kernel(const int* __restrict__ ei) {
    int e = blockIdx.x * blockDim.x + threadIdx.x;
    if (e >= ET) return;
    int dst = (e < EE) ? ei[EE + e] : (e - EE);
    atomicAdd(&g_cnt[dst], 1);
}
__global__ void scan_kernel() {
    __shared__ int sh[1024];
    __shared__ int carry_s;
    int tid = threadIdx.x;
    if (tid == 0) carry_s = 0;
    __syncthreads();
    for (int base = 0; base < NN; base += 1024) {
        int i = base + tid;
        int v = (i < NN) ? g_cnt[i] : 0;
        sh[tid] = v;
        __syncthreads();
        for (int off = 1; off < 1024; off <<= 1) {
            int t = (tid >= off) ? sh[tid - off] : 0;
            __syncthreads();
            sh[tid] += t;
            __syncthreads();
        }
        int incl = sh[tid];
        int c = carry_s;
        if (i < NN) { g_off[i] = c + incl - v; g_cur[i] = c + incl - v; }
        __syncthreads();
        if (tid == 1023) carry_s = c + sh[1023];
        __syncthreads();
    }
    if (tid == 0) g_off[NN] = carry_s;
}
__global__ void scatter_kernel(const int* __restrict__ ei) {
    int e = blockIdx.x * blockDim.x + threadIdx.x;
    if (e >= ET) return;
    int src, dst;
    if (e < EE) { src = ei[e]; dst = ei[EE + e]; }
    else        { src = e - EE; dst = src; }
    int p = atomicAdd(&g_cur[dst], 1);
    g_esrc[p] = src;
}

// ---------------- W transpose + bf16 split ---------------------------------
__global__ void convW_kernel(const float* __restrict__ W, __nv_bfloat16* __restrict__ Th,
                             __nv_bfloat16* __restrict__ Tl, int K, int Ncol) {
    int idx = blockIdx.x * blockDim.x + threadIdx.x;
    if (idx >= K * Ncol) return;
    int n = idx / K, k = idx % K;
    float v = W[(size_t)k * Ncol + n];
    __nv_bfloat16 hh = __float2bfloat16(v);
    Th[idx] = hh;
    Tl[idx] = __float2bfloat16(v - __bfloat162float(hh));
}

// ---------------- mma.sync bf16 helper -------------------------------------
__device__ __forceinline__ void mma16816(float* c, const uint32_t* a, const uint32_t* b) {
    asm volatile(
        "mma.sync.aligned.m16n8k16.row.col.f32.bf16.bf16.f32 "
        "{%0,%1,%2,%3}, {%4,%5,%6,%7}, {%8,%9}, {%0,%1,%2,%3};"
        : "+f"(c[0]), "+f"(c[1]), "+f"(c[2]), "+f"(c[3])
        : "r"(a[0]), "r"(a[1]), "r"(a[2]), "r"(a[3]), "r"(b[0]), "r"(b[1]));
}

// ---------------- bf16-split GEMM via mma.sync + fused alpha epilogue ------
// Block: 256 thr = 8 warps (4 in M x 2 in N). BM=128, BN=CH (one head), BK=64.
// C = A(fp32->bf16 hi/lo) @ WT^T with 3 terms: AhBh + AhBl + AlBh.
template<int CH>
__global__ void __launch_bounds__(256)
gemm_gat(const float* __restrict__ A, const __nv_bfloat16* __restrict__ BTh,
         const __nv_bfloat16* __restrict__ BTl, float* __restrict__ C,
         float* __restrict__ as_o, float* __restrict__ ad_o,
         const float* __restrict__ a_src, const float* __restrict__ a_dst,
         int M, int K, int NH) {
    constexpr int SP = 72;                 // smem row stride in halves (pad)
    constexpr int CHW = CH / 2;            // cols per N-warp (32 or 16)
    constexpr int NT = CH / 16;            // n-tiles (8 wide) per warp (4 or 2)
    extern __shared__ char smem[];
    __nv_bfloat16* Ahi = (__nv_bfloat16*)(smem);
    __nv_bfloat16* Alo = Ahi + 128 * SP;
    __nv_bfloat16* Bhi = Alo + 128 * SP;
    __nv_bfloat16* Blo = Bhi + CH * SP;
    float* asbuf = (float*)(Blo + CH * SP);   // [128][2]
    float* adbuf = asbuf + 128 * 2;

    const int tid = threadIdx.x, wid = tid >> 5, lane = tid & 31;
    const int wm = wid & 3, wn = wid >> 2;
    const int gid = lane >> 2, tig = lane & 3;
    const int bm = blockIdx.y * 128;
    const int h = blockIdx.x;

    const __nv_bfloat16* bh = BTh + (size_t)h * CH * K;
    const __nv_bfloat16* bl = BTl + (size_t)h * CH * K;

    float c[2][NT][4];
#pragma unroll
    for (int i = 0; i < 2; i++)
#pragma unroll
        for (int j = 0; j < NT; j++)
#pragma unroll
            for (int q = 0; q < 4; q++) c[i][j][q] = 0.f;

    const int nch = K >> 6;
    for (int ch = 0; ch < nch; ch++) {
        const int k0 = ch << 6;
        // ---- A tile: 128 x 64 fp32 -> bf16 hi/lo ----
#pragma unroll
        for (int it = 0; it < 4; it++) {
            int s = tid + it * 256;
            int r = s >> 3, t8 = s & 7;
            const float* ap = A + (size_t)min(bm + r, M - 1) * K + k0 + t8 * 8;
            float4 v0 = *(const float4*)ap;
            float4 v1 = *(const float4*)(ap + 4);
            float f[8] = {v0.x, v0.y, v0.z, v0.w, v1.x, v1.y, v1.z, v1.w};
            uint32_t hiw[4], low[4];
#pragma unroll
            for (int j = 0; j < 4; j++) {
                __nv_bfloat16 h0 = __float2bfloat16(f[2 * j]);
                __nv_bfloat16 h1 = __float2bfloat16(f[2 * j + 1]);
                __nv_bfloat162 ph(h0, h1);
                __nv_bfloat162 pl(__float2bfloat16(f[2 * j] - __bfloat162float(h0)),
                                  __float2bfloat16(f[2 * j + 1] - __bfloat162float(h1)));
                hiw[j] = *(uint32_t*)&ph;
                low[j] = *(uint32_t*)&pl;
            }
            *(uint4*)&Ahi[r * SP + t8 * 8] = make_uint4(hiw[0], hiw[1], hiw[2], hiw[3]);
            *(uint4*)&Alo[r * SP + t8 * 8] = make_uint4(low[0], low[1], low[2], low[3]);
        }
        // ---- B tile: CH x 64 bf16 (already split) ----
#pragma unroll
        for (int it = 0; it < CH * 8 / 256; it++) {
            int s = tid + it * 256;
            int n = s >> 3, t8 = s & 7;
            *(uint4*)&Bhi[n * SP + t8 * 8] = *(const uint4*)(bh + (size_t)n * K + k0 + t8 * 8);
            *(uint4*)&Blo[n * SP + t8 * 8] = *(const uint4*)(bl + (size_t)n * K + k0 + t8 * 8);
        }
        __syncthreads();
        // ---- compute: 4 k16 steps ----
#pragma unroll
        for (int kk = 0; kk < 4; kk++) {
            const int kb = kk * 16 + tig * 2;
            uint32_t ah[2][4], al[2][4], bhf[NT][2], blf[NT][2];
#pragma unroll
            for (int mt = 0; mt < 2; mt++) {
                int r0 = (wm * 32 + mt * 16 + gid) * SP + kb;
                ah[mt][0] = *(const uint32_t*)&Ahi[r0];
                ah[mt][1] = *(const uint32_t*)&Ahi[r0 + 8 * SP];
                ah[mt][2] = *(const uint32_t*)&Ahi[r0 + 8];
                ah[mt][3] = *(const uint32_t*)&Ahi[r0 + 8 * SP + 8];
                al[mt][0] = *(const uint32_t*)&Alo[r0];
                al[mt][1] = *(const uint32_t*)&Alo[r0 + 8 * SP];
                al[mt][2] = *(const uint32_t*)&Alo[r0 + 8];
                al[mt][3] = *(const uint32_t*)&Alo[r0 + 8 * SP + 8];
            }
#pragma unroll
            for (int nt = 0; nt < NT; nt++) {
                int n0 = (wn * CHW + nt * 8 + gid) * SP + kb;
                bhf[nt][0] = *(const uint32_t*)&Bhi[n0];
                bhf[nt][1] = *(const uint32_t*)&Bhi[n0 + 8];
                blf[nt][0] = *(const uint32_t*)&Blo[n0];
                blf[nt][1] = *(const uint32_t*)&Blo[n0 + 8];
            }
#pragma unroll
            for (int mt = 0; mt < 2; mt++)
#pragma unroll
                for (int nt = 0; nt < NT; nt++) {
                    mma16816(c[mt][nt], ah[mt], bhf[nt]);
                    mma16816(c[mt][nt], ah[mt], blf[nt]);
                    mma16816(c[mt][nt], al[mt], bhf[nt]);
                }
        }
        __syncthreads();
    }

    // ---- epilogue: write C + fused alpha dots ----
    // C frag mapping: c0:(row gid, col tig*2) c1:(gid, tig*2+1) c2:(gid+8,..) c3
    float pa[2][2], pd[2][2];   // [mt][r2]
#pragma unroll
    for (int mt = 0; mt < 2; mt++)
#pragma unroll
        for (int r2 = 0; r2 < 2; r2++) { pa[mt][r2] = 0.f; pd[mt][r2] = 0.f; }
#pragma unroll
    for (int mt = 0; mt < 2; mt++) {
#pragma unroll
        for (int nt = 0; nt < NT; nt++) {
            int col = wn * CHW + nt * 8 + tig * 2;
            int row0 = bm + wm * 32 + mt * 16 + gid;
            float s0 = a_src[h * CH + col], s1 = a_src[h * CH + col + 1];
            float d0 = a_dst[h * CH + col], d1 = a_dst[h * CH + col + 1];
            pa[mt][0] += c[mt][nt][0] * s0 + c[mt][nt][1] * s1;
            pd[mt][0] += c[mt][nt][0] * d0 + c[mt][nt][1] * d1;
            pa[mt][1] += c[mt][nt][2] * s0 + c[mt][nt][3] * s1;
            pd[mt][1] += c[mt][nt][2] * d0 + c[mt][nt][3] * d1;
            if (row0 < M)
                *(float2*)&C[(size_t)row0 * NH * CH + h * CH + col] =
                    make_float2(c[mt][nt][0], c[mt][nt][1]);
            if (row0 + 8 < M)
                *(float2*)&C[(size_t)(row0 + 8) * NH * CH + h * CH + col] =
                    make_float2(c[mt][nt][2], c[mt][nt][3]);
        }
    }
    // quad-reduce (lanes gid*4 .. gid*4+3 hold the 4 col-groups of each row)
#pragma unroll
    for (int mt = 0; mt < 2; mt++)
#pragma unroll
        for (int r2 = 0; r2 < 2; r2++) {
#pragma unroll
            for (int o = 1; o < 4; o <<= 1) {
                pa[mt][r2] += __shfl_xor_sync(0xffffffffu, pa[mt][r2], o);
                pd[mt][r2] += __shfl_xor_sync(0xffffffffu, pd[mt][r2], o);
            }
            if (tig == 0) {
                int rl = wm * 32 + mt * 16 + r2 * 8 + gid;
                asbuf[rl * 2 + wn] = pa[mt][r2];
                adbuf[rl * 2 + wn] = pd[mt][r2];
            }
        }
    __syncthreads();
    if (tid < 128) {
        int row = bm + tid;
        if (row < M) {
            as_o[row * NH + h] = asbuf[tid * 2] + asbuf[tid * 2 + 1];
            ad_o[row * NH + h] = adbuf[tid * 2] + adbuf[tid * 2 + 1];
        }
    }
}

// ---------------- gather-side online-softmax aggregation -------------------
template<int C, int NH, bool RELU, bool LSM>
__global__ void agg_kernel(const float* __restrict__ h, const float* __restrict__ as,
                           const float* __restrict__ ad, const float* __restrict__ bias,
                           float* __restrict__ out) {
    int gw = (blockIdx.x * blockDim.x + threadIdx.x) >> 5;
    int lane = threadIdx.x & 31;
    if (gw >= NN * NH) return;
    int n = gw / NH, hh = gw % NH;
    int beg = g_off[n], end = g_off[n + 1];
    float adn = ad[gw];
    constexpr int CPL = C / 32;
    float acc[CPL];
#pragma unroll
    for (int j = 0; j < CPL; j++) acc[j] = 0.f;
    float m = -1e30f, dsum = 0.f;
    for (int i = beg; i < end; i++) {
        int s = g_esrc[i];
        float e = as[s * NH + hh] + adn;
        e = e > 0.f ? e : 0.2f * e;                 // leaky relu
        float mn = fmaxf(m, e);
        float sc = __expf(m - mn);
        float w  = __expf(e - mn);
        dsum = dsum * sc + w;
        const float* hp = h + (size_t)s * NH * C + hh * C;
#pragma unroll
        for (int j = 0; j < CPL; j++)
            acc[j] = acc[j] * sc + w * __ldg(&hp[lane + 32 * j]);
        m = mn;
    }
    float inv = 1.f / (dsum + 1e-16f);
    if (!LSM) {
#pragma unroll
        for (int j = 0; j < CPL; j++) {
            float r = acc[j] * inv + bias[hh * C + lane + 32 * j];
            if (RELU) r = fmaxf(r, 0.f);
            out[(size_t)n * NH * C + hh * C + lane + 32 * j] = r;
        }
    } else {
        float r = acc[0] * inv + bias[lane];
        float mx = r;
#pragma unroll
        for (int o = 16; o; o >>= 1) mx = fmaxf(mx, __shfl_xor_sync(0xffffffffu, mx, o));
        float ex = __expf(r - mx);
        float sm = ex;
#pragma unroll
        for (int o = 16; o; o >>= 1) sm += __shfl_xor_sync(0xffffffffu, sm, o);
        out[(size_t)n * 32 + lane] = r - mx - logf(sm);
    }
}

// ---------------- launch ---------------------------------------------------
extern "C" void kernel_launch(void* const* d_in, const int* in_sizes, int n_in,
                              void* d_out, int out_size) {
    const float* x   = (const float*)d_in[0];
    const int*   ei  = (const int*)d_in[1];
    const float* W1  = (const float*)d_in[2];
    const float* a1s = (const float*)d_in[3];
    const float* a1d = (const float*)d_in[4];
    const float* b1  = (const float*)d_in[5];
    const float* W2  = (const float*)d_in[6];
    const float* a2s = (const float*)d_in[7];
    const float* a2d = (const float*)d_in[8];
    const float* b2  = (const float*)d_in[9];
    const float* W3  = (const float*)d_in[10];
    const float* a3s = (const float*)d_in[11];
    const float* a3d = (const float*)d_in[12];
    const float* b3  = (const float*)d_in[13];
    float* out = (float*)d_out;

    float *bufA, *bufB, *bufC, *pas, *pad_;
    __nv_bfloat16 *wt1h, *wt1l, *wt2h, *wt2l, *wt3h, *wt3l;
    cudaGetSymbolAddress((void**)&bufA, g_bufA);
    cudaGetSymbolAddress((void**)&bufB, g_bufB);
    cudaGetSymbolAddress((void**)&bufC, g_bufC);
    cudaGetSymbolAddress((void**)&pas, g_as);
    cudaGetSymbolAddress((void**)&pad_, g_ad);
    cudaGetSymbolAddress((void**)&wt1h, g_wt1h);
    cudaGetSymbolAddress((void**)&wt1l, g_wt1l);
    cudaGetSymbolAddress((void**)&wt2h, g_wt2h);
    cudaGetSymbolAddress((void**)&wt2l, g_wt2l);
    cudaGetSymbolAddress((void**)&wt3h, g_wt3h);
    cudaGetSymbolAddress((void**)&wt3l, g_wt3l);

    // dynamic smem: A(hi+lo) 128*72 + B(hi+lo) CH*72 halves + 2*128*2 floats
    const int SMEM64 = (2 * 128 * 72 + 2 * 64 * 72) * 2 + 2 * 128 * 2 * 4;  // 57344
    const int SMEM32 = (2 * 128 * 72 + 2 * 32 * 72) * 2 + 2 * 128 * 2 * 4;  // 48128
    cudaFuncSetAttribute(gemm_gat<64>, cudaFuncAttributeMaxDynamicSharedMemorySize, SMEM64);
    cudaFuncSetAttribute(gemm_gat<32>, cudaFuncAttributeMaxDynamicSharedMemorySize, SMEM32);

    // ---- CSR by destination ----
    zero_cnt_kernel<<<(NN + 255) / 256, 256>>>();
    hist_kernel<<<(ET + 255) / 256, 256>>>(ei);
    scan_kernel<<<1, 1024>>>();
    scatter_kernel<<<(ET + 255) / 256, 256>>>(ei);

    // ---- weight transpose + split ----
    convW_kernel<<<(448 * 256 + 255) / 256, 256>>>(W1, wt1h, wt1l, 256, 448);
    convW_kernel<<<(448 * 448 + 255) / 256, 256>>>(W2, wt2h, wt2l, 448, 448);
    convW_kernel<<<(32 * 448 + 255) / 256, 256>>>(W3, wt3h, wt3l, 448, 32);

    const int MB = (NN + 127) / 128;              // 391
    const int wb12 = (NN * 7 * 32 + 255) / 256;
    const int wb3  = (NN * 1 * 32 + 255) / 256;

    // ---- layer 1 ----
    gemm_gat<64><<<dim3(7, MB), 256, SMEM64>>>(x, wt1h, wt1l, bufA, pas, pad_, a1s, a1d, NN, 256, 7);
    agg_kernel<64, 7, true, false><<<wb12, 256>>>(bufA, pas, pad_, b1, bufB);

    // ---- layer 2 ----
    gemm_gat<64><<<dim3(7, MB), 256, SMEM64>>>(bufB, wt2h, wt2l, bufA, pas, pad_, a2s, a2d, NN, 448, 7);
    agg_kernel<64, 7, true, false><<<wb12, 256>>>(bufA, pas, pad_, b2, bufB);

    // ---- layer 3 (+ fused log_softmax) ----
    gemm_gat<32><<<dim3(1, MB), 256, SMEM32>>>(bufB, wt3h, wt3l, bufC, pas, pad_, a3s, a3d, NN, 448, 1);
    agg_kernel<32, 1, false, true><<<wb3, 256>>>(bufC, pas, pad_, b3, out);
}

// round 7
// speedup vs baseline: 1.4264x; 1.0025x over previous
#include <cuda_runtime.h>
#include <cuda_bf16.h>
#include <cstdint>

#define NN 50000
#define EE 800000
#define ET (EE + NN)          // edges + self loops
#define F12 448               // 7 heads * 64 ch
#define F3  32

// ---------------- scratch (static device globals; no allocation allowed) ----
__device__ __align__(128) float g_bufA[(size_t)NN * F12];  // GEMM output h (fp32)
__device__ __align__(128) float g_bufC[(size_t)NN * F3];   // layer-3 h
__device__ __align__(128) __nv_bfloat16 g_xh[(size_t)NN * 256], g_xl[(size_t)NN * 256];
__device__ __align__(128) __nv_bfloat16 g_ah[(size_t)NN * F12], g_al[(size_t)NN * F12];
__device__ float g_as[NN * 7];
__device__ float g_ad[NN * 7];
__device__ int g_cnt[NN];
__device__ int g_off[NN + 1];
__device__ int g_cur[NN];
__device__ int g_esrc[ET];
// transposed + bf16-split weights: WT[n*K + k] = W[k*N + n]
__device__ __align__(128) __nv_bfloat16 g_wt1h[448 * 256], g_wt1l[448 * 256];
__device__ __align__(128) __nv_bfloat16 g_wt2h[448 * 448], g_wt2l[448 * 448];
__device__ __align__(128) __nv_bfloat16 g_wt3h[32 * 448],  g_wt3l[32 * 448];

// ---------------- CSR build ------------------------------------------------
__global__ void zero_cnt_kernel() {
    int i = blockIdx.x * blockDim.x + threadIdx.x;
    if (i < NN) g_cnt[i] = 0;
}
__global__ void hist_kernel(const int* __restrict__ ei) {
    int e = blockIdx.x * blockDim.x + threadIdx.x;
    if (e >= ET) return;
    int dst = (e < EE) ? ei[EE + e] : (e - EE);
    atomicAdd(&g_cnt[dst], 1);
}
__global__ void scan_kernel() {
    __shared__ int sh[1024];
    __shared__ int carry_s;
    int tid = threadIdx.x;
    if (tid == 0) carry_s = 0;
    __syncthreads();
    for (int base = 0; base < NN; base += 1024) {
        int i = base + tid;
        int v = (i < NN) ? g_cnt[i] : 0;
        sh[tid] = v;
        __syncthreads();
        for (int off = 1; off < 1024; off <<= 1) {
            int t = (tid >= off) ? sh[tid - off] : 0;
            __syncthreads();
            sh[tid] += t;
            __syncthreads();
        }
        int incl = sh[tid];
        int c = carry_s;
        if (i < NN) { g_off[i] = c + incl - v; g_cur[i] = c + incl - v; }
        __syncthreads();
        if (tid == 1023) carry_s = c + sh[1023];
        __syncthreads();
    }
    if (tid == 0) g_off[NN] = carry_s;
}
__global__ void scatter_kernel(const int* __restrict__ ei) {
    int e = blockIdx.x * blockDim.x + threadIdx.x;
    if (e >= ET) return;
    int src, dst;
    if (e < EE) { src = ei[e]; dst = ei[EE + e]; }
    else        { src = e - EE; dst = src; }
    int p = atomicAdd(&g_cur[dst], 1);
    g_esrc[p] = src;
}

// ---------------- W transpose + bf16 split ---------------------------------
__global__ void convW_kernel(const float* __restrict__ W, __nv_bfloat16* __restrict__ Th,
                             __nv_bfloat16* __restrict__ Tl, int K, int Ncol) {
    int idx = blockIdx.x * blockDim.x + threadIdx.x;
    if (idx >= K * Ncol) return;
    int n = idx / K, k = idx % K;
    float v = W[(size_t)k * Ncol + n];
    __nv_bfloat16 hh = __float2bfloat16(v);
    Th[idx] = hh;
    Tl[idx] = __float2bfloat16(v - __bfloat162float(hh));
}

// ---------------- x split (fp32 -> bf16 hi/lo) -----------------------------
__global__ void splitX_kernel(const float* __restrict__ x, __nv_bfloat16* __restrict__ xh,
                              __nv_bfloat16* __restrict__ xl, int total4) {
    int i = blockIdx.x * blockDim.x + threadIdx.x;
    if (i >= total4) return;
    float4 v = *(const float4*)(x + (size_t)i * 4);
    float f[4] = {v.x, v.y, v.z, v.w};
    __nv_bfloat16 h[4], l[4];
#pragma unroll
    for (int j = 0; j < 4; j++) {
        h[j] = __float2bfloat16(f[j]);
        l[j] = __float2bfloat16(f[j] - __bfloat162float(h[j]));
    }
    *(uint2*)(xh + (size_t)i * 4) = *(uint2*)h;
    *(uint2*)(xl + (size_t)i * 4) = *(uint2*)l;
}

// ---------------- mma / ldmatrix helpers -----------------------------------
__device__ __forceinline__ void mma16816(float* c, const uint32_t* a, const uint32_t* b) {
    asm volatile(
        "mma.sync.aligned.m16n8k16.row.col.f32.bf16.bf16.f32 "
        "{%0,%1,%2,%3}, {%4,%5,%6,%7}, {%8,%9}, {%0,%1,%2,%3};"
        : "+f"(c[0]), "+f"(c[1]), "+f"(c[2]), "+f"(c[3])
        : "r"(a[0]), "r"(a[1]), "r"(a[2]), "r"(a[3]), "r"(b[0]), "r"(b[1]));
}
__device__ __forceinline__ void ldsm4(uint32_t& r0, uint32_t& r1, uint32_t& r2, uint32_t& r3,
                                      uint32_t addr) {
    asm volatile("ldmatrix.sync.aligned.m8n8.x4.shared.b16 {%0,%1,%2,%3}, [%4];"
        : "=r"(r0), "=r"(r1), "=r"(r2), "=r"(r3) : "r"(addr));
}
__device__ __forceinline__ uint32_t smem_u32(const void* p) {
    uint32_t a;
    asm("{ .reg .u64 t; cvta.to.shared.u64 t, %1; cvt.u32.u64 %0, t; }" : "=r"(a) : "l"(p));
    return a;
}

// ---------------- bf16-split GEMM (pre-split A) + fused alpha epilogue -----
// Block: 256 thr = 8 warps (4 in M x 2 in N). BM=128, BN=CH (one head), BK=64.
// C = (Ah+Al) @ (Bh+Bl)^T via 3 terms: AhBh + AhBl + AlBh.
template<int CH>
__global__ void __launch_bounds__(256)
gemm_gat(const __nv_bfloat16* __restrict__ Agh, const __nv_bfloat16* __restrict__ Agl,
         const __nv_bfloat16* __restrict__ BTh, const __nv_bfloat16* __restrict__ BTl,
         float* __restrict__ C, float* __restrict__ as_o, float* __restrict__ ad_o,
         const float* __restrict__ a_src, const float* __restrict__ a_dst,
         int M, int K, int NH) {
    constexpr int SP = 72;                 // smem row stride in halves (pad)
    constexpr int CHW = CH / 2;            // cols per N-warp
    constexpr int NT = CH / 16;            // 8-wide n-tiles per warp
    extern __shared__ char smem[];
    __nv_bfloat16* Ahi = (__nv_bfloat16*)(smem);
    __nv_bfloat16* Alo = Ahi + 128 * SP;
    __nv_bfloat16* Bhi = Alo + 128 * SP;
    __nv_bfloat16* Blo = Bhi + CH * SP;
    float* asbuf = (float*)(Blo + CH * SP);   // [128][2]
    float* adbuf = asbuf + 128 * 2;

    const int tid = threadIdx.x, wid = tid >> 5, lane = tid & 31;
    const int wm = wid & 3, wn = wid >> 2;
    const int gid = lane >> 2, tig = lane & 3;
    const int bm = blockIdx.y * 128;
    const int h = blockIdx.x;

    const __nv_bfloat16* bh = BTh + (size_t)h * CH * K;
    const __nv_bfloat16* bl = BTl + (size_t)h * CH * K;

    const uint32_t sAhi = smem_u32(Ahi), sAlo = smem_u32(Alo);
    const uint32_t sBhi = smem_u32(Bhi), sBlo = smem_u32(Blo);
    // ldmatrix per-lane offsets (in halves)
    const int aoff = (wm * 32 + (lane & 15)) * SP + ((lane >> 4) << 3);
    const int boff = (wn * CHW + (lane & 7) + ((lane & 16) ? 8 : 0)) * SP + ((lane & 8) ? 8 : 0);

    float c[2][NT][4];
#pragma unroll
    for (int i = 0; i < 2; i++)
#pragma unroll
        for (int j = 0; j < NT; j++)
#pragma unroll
            for (int q = 0; q < 4; q++) c[i][j][q] = 0.f;

    const int nch = K >> 6;
    for (int ch = 0; ch < nch; ch++) {
        const int k0 = ch << 6;
        // ---- A tile: 128 x 64 halves, hi + lo (pure copies) ----
#pragma unroll
        for (int it = 0; it < 4; it++) {
            int s = tid + it * 256;
            int r = s >> 3, t8 = s & 7;
            size_t gidx = (size_t)min(bm + r, M - 1) * K + k0 + t8 * 8;
            *(uint4*)&Ahi[r * SP + t8 * 8] = *(const uint4*)(Agh + gidx);
            *(uint4*)&Alo[r * SP + t8 * 8] = *(const uint4*)(Agl + gidx);
        }
        // ---- B tile: CH x 64 halves ----
#pragma unroll
        for (int it = 0; it < CH * 8 / 256; it++) {
            int s = tid + it * 256;
            int n = s >> 3, t8 = s & 7;
            *(uint4*)&Bhi[n * SP + t8 * 8] = *(const uint4*)(bh + (size_t)n * K + k0 + t8 * 8);
            *(uint4*)&Blo[n * SP + t8 * 8] = *(const uint4*)(bl + (size_t)n * K + k0 + t8 * 8);
        }
        __syncthreads();
        // ---- compute: 4 k16 steps, ldmatrix fragments ----
#pragma unroll
        for (int kk = 0; kk < 4; kk++) {
            const int kb = kk * 16;
            uint32_t ah[2][4], al[2][4];
#pragma unroll
            for (int mt = 0; mt < 2; mt++) {
                uint32_t off = (uint32_t)(aoff + mt * 16 * SP + kb) * 2;
                ldsm4(ah[mt][0], ah[mt][1], ah[mt][2], ah[mt][3], sAhi + off);
                ldsm4(al[mt][0], al[mt][1], al[mt][2], al[mt][3], sAlo + off);
            }
            uint32_t bhf[NT][2], blf[NT][2];
#pragma unroll
            for (int tp = 0; tp < NT / 2; tp++) {
                uint32_t off = (uint32_t)(boff + tp * 16 * SP + kb) * 2;
                ldsm4(bhf[2 * tp][0], bhf[2 * tp][1], bhf[2 * tp + 1][0], bhf[2 * tp + 1][1], sBhi + off);
                ldsm4(blf[2 * tp][0], blf[2 * tp][1], blf[2 * tp + 1][0], blf[2 * tp + 1][1], sBlo + off);
            }
#pragma unroll
            for (int mt = 0; mt < 2; mt++)
#pragma unroll
                for (int nt = 0; nt < NT; nt++) {
                    mma16816(c[mt][nt], ah[mt], bhf[nt]);
                    mma16816(c[mt][nt], ah[mt], blf[nt]);
                    mma16816(c[mt][nt], al[mt], bhf[nt]);
                }
        }
        __syncthreads();
    }

    // ---- epilogue: write C + fused alpha dots ----
    float pa[2][2], pd[2][2];
#pragma unroll
    for (int mt = 0; mt < 2; mt++)
#pragma unroll
        for (int r2 = 0; r2 < 2; r2++) { pa[mt][r2] = 0.f; pd[mt][r2] = 0.f; }
#pragma unroll
    for (int mt = 0; mt < 2; mt++) {
#pragma unroll
        for (int nt = 0; nt < NT; nt++) {
            int col = wn * CHW + nt * 8 + tig * 2;
            int row0 = bm + wm * 32 + mt * 16 + gid;
            float s0 = a_src[h * CH + col], s1 = a_src[h * CH + col + 1];
            float d0 = a_dst[h * CH + col], d1 = a_dst[h * CH + col + 1];
            pa[mt][0] += c[mt][nt][0] * s0 + c[mt][nt][1] * s1;
            pd[mt][0] += c[mt][nt][0] * d0 + c[mt][nt][1] * d1;
            pa[mt][1] += c[mt][nt][2] * s0 + c[mt][nt][3] * s1;
            pd[mt][1] += c[mt][nt][2] * d0 + c[mt][nt][3] * d1;
            if (row0 < M)
                *(float2*)&C[(size_t)row0 * NH * CH + h * CH + col] =
                    make_float2(c[mt][nt][0], c[mt][nt][1]);
            if (row0 + 8 < M)
                *(float2*)&C[(size_t)(row0 + 8) * NH * CH + h * CH + col] =
                    make_float2(c[mt][nt][2], c[mt][nt][3]);
        }
    }
#pragma unroll
    for (int mt = 0; mt < 2; mt++)
#pragma unroll
        for (int r2 = 0; r2 < 2; r2++) {
#pragma unroll
            for (int o = 1; o < 4; o <<= 1) {
                pa[mt][r2] += __shfl_xor_sync(0xffffffffu, pa[mt][r2], o);
                pd[mt][r2] += __shfl_xor_sync(0xffffffffu, pd[mt][r2], o);
            }
            if (tig == 0) {
                int rl = wm * 32 + mt * 16 + r2 * 8 + gid;
                asbuf[rl * 2 + wn] = pa[mt][r2];
                adbuf[rl * 2 + wn] = pd[mt][r2];
            }
        }
    __syncthreads();
    if (tid < 128) {
        int row = bm + tid;
        if (row < M) {
            as_o[row * NH + h] = asbuf[tid * 2] + asbuf[tid * 2 + 1];
            ad_o[row * NH + h] = adbuf[tid * 2] + adbuf[tid * 2 + 1];
        }
    }
}

// ---------------- gather-side online-softmax aggregation -------------------
// non-LSM: writes bf16 hi/lo split output (input for the next GEMM)
template<int C, int NH, bool RELU, bool LSM>
__global__ void agg_kernel(const float* __restrict__ h, const float* __restrict__ as,
                           const float* __restrict__ ad, const float* __restrict__ bias,
                           float* __restrict__ out, __nv_bfloat16* __restrict__ oh,
                           __nv_bfloat16* __restrict__ ol) {
    int gw = (blockIdx.x * blockDim.x + threadIdx.x) >> 5;
    int lane = threadIdx.x & 31;
    if (gw >= NN * NH) return;
    int n = gw / NH, hh = gw % NH;
    int beg = g_off[n], end = g_off[n + 1];
    float adn = ad[gw];
    constexpr int CPL = C / 32;
    float acc[CPL];
#pragma unroll
    for (int j = 0; j < CPL; j++) acc[j] = 0.f;
    float m = -1e30f, dsum = 0.f;
    for (int i = beg; i < end; i++) {
        int s = g_esrc[i];
        float e = as[s * NH + hh] + adn;
        e = e > 0.f ? e : 0.2f * e;                 // leaky relu
        float mn = fmaxf(m, e);
        float sc = __expf(m - mn);
        float w  = __expf(e - mn);
        dsum = dsum * sc + w;
        const float* hp = h + (size_t)s * NH * C + hh * C;
#pragma unroll
        for (int j = 0; j < CPL; j++)
            acc[j] = acc[j] * sc + w * __ldg(&hp[lane + 32 * j]);
        m = mn;
    }
    float inv = 1.f / (dsum + 1e-16f);
    if (!LSM) {
#pragma unroll
        for (int j = 0; j < CPL; j++) {
            float r = acc[j] * inv + bias[hh * C + lane + 32 * j];
            if (RELU) r = fmaxf(r, 0.f);
            size_t idx = (size_t)n * NH * C + hh * C + lane + 32 * j;
            __nv_bfloat16 hi = __float2bfloat16(r);
            oh[idx] = hi;
            ol[idx] = __float2bfloat16(r - __bfloat162float(hi));
        }
    } else {
        float r = acc[0] * inv + bias[lane];
        float mx = r;
#pragma unroll
        for (int o = 16; o; o >>= 1) mx = fmaxf(mx, __shfl_xor_sync(0xffffffffu, mx, o));
        float ex = __expf(r - mx);
        float sm = ex;
#pragma unroll
        for (int o = 16; o; o >>= 1) sm += __shfl_xor_sync(0xffffffffu, sm, o);
        out[(size_t)n * 32 + lane] = r - mx - logf(sm);
    }
}

// ---------------- launch ---------------------------------------------------
extern "C" void kernel_launch(void* const* d_in, const int* in_sizes, int n_in,
                              void* d_out, int out_size) {
    const float* x   = (const float*)d_in[0];
    const int*   ei  = (const int*)d_in[1];
    const float* W1  = (const float*)d_in[2];
    const float* a1s = (const float*)d_in[3];
    const float* a1d = (const float*)d_in[4];
    const float* b1  = (const float*)d_in[5];
    const float* W2  = (const float*)d_in[6];
    const float* a2s = (const float*)d_in[7];
    const float* a2d = (const float*)d_in[8];
    const float* b2  = (const float*)d_in[9];
    const float* W3  = (const float*)d_in[10];
    const float* a3s = (const float*)d_in[11];
    const float* a3d = (const float*)d_in[12];
    const float* b3  = (const float*)d_in[13];
    float* out = (float*)d_out;

    float *bufA, *bufC, *pas, *pad_;
    __nv_bfloat16 *xh, *xl, *ah, *al;
    __nv_bfloat16 *wt1h, *wt1l, *wt2h, *wt2l, *wt3h, *wt3l;
    cudaGetSymbolAddress((void**)&bufA, g_bufA);
    cudaGetSymbolAddress((void**)&bufC, g_bufC);
    cudaGetSymbolAddress((void**)&pas, g_as);
    cudaGetSymbolAddress((void**)&pad_, g_ad);
    cudaGetSymbolAddress((void**)&xh, g_xh);
    cudaGetSymbolAddress((void**)&xl, g_xl);
    cudaGetSymbolAddress((void**)&ah, g_ah);
    cudaGetSymbolAddress((void**)&al, g_al);
    cudaGetSymbolAddress((void**)&wt1h, g_wt1h);
    cudaGetSymbolAddress((void**)&wt1l, g_wt1l);
    cudaGetSymbolAddress((void**)&wt2h, g_wt2h);
    cudaGetSymbolAddress((void**)&wt2l, g_wt2l);
    cudaGetSymbolAddress((void**)&wt3h, g_wt3h);
    cudaGetSymbolAddress((void**)&wt3l, g_wt3l);

    const int SMEM64 = (2 * 128 * 72 + 2 * 64 * 72) * 2 + 2 * 128 * 2 * 4;  // 57344
    const int SMEM32 = (2 * 128 * 72 + 2 * 32 * 72) * 2 + 2 * 128 * 2 * 4;  // 48128
    cudaFuncSetAttribute(gemm_gat<64>, cudaFuncAttributeMaxDynamicSharedMemorySize, SMEM64);
    cudaFuncSetAttribute(gemm_gat<32>, cudaFuncAttributeMaxDynamicSharedMemorySize, SMEM32);

    // ---- CSR by destination ----
    zero_cnt_kernel<<<(NN + 255) / 256, 256>>>();
    hist_kernel<<<(ET + 255) / 256, 256>>>(ei);
    scan_kernel<<<1, 1024>>>();
    scatter_kernel<<<(ET + 255) / 256, 256>>>(ei);

    // ---- weight transpose + split, x split ----
    convW_kernel<<<(448 * 256 + 255) / 256, 256>>>(W1, wt1h, wt1l, 256, 448);
    convW_kernel<<<(448 * 448 + 255) / 256, 256>>>(W2, wt2h, wt2l, 448, 448);
    convW_kernel<<<(32 * 448 + 255) / 256, 256>>>(W3, wt3h, wt3l, 448, 32);
    splitX_kernel<<<(NN * 256 / 4 + 255) / 256, 256>>>(x, xh, xl, NN * 256 / 4);

    const int MB = (NN + 127) / 128;              // 391
    const int wb12 = (NN * 7 * 32 + 255) / 256;
    const int wb3  = (NN * 1 * 32 + 255) / 256;

    // ---- layer 1 ----
    gemm_gat<64><<<dim3(7, MB), 256, SMEM64>>>(xh, xl, wt1h, wt1l, bufA, pas, pad_, a1s, a1d, NN, 256, 7);
    agg_kernel<64, 7, true, false><<<wb12, 256>>>(bufA, pas, pad_, b1, nullptr, ah, al);

    // ---- layer 2 ----
    gemm_gat<64><<<dim3(7, MB), 256, SMEM64>>>(ah, al, wt2h, wt2l, bufA, pas, pad_, a2s, a2d, NN, 448, 7);
    agg_kernel<64, 7, true, false><<<wb12, 256>>>(bufA, pas, pad_, b2, nullptr, ah, al);

    // ---- layer 3 (+ fused log_softmax) ----
    gemm_gat<32><<<dim3(1, MB), 256, SMEM32>>>(ah, al, wt3h, wt3l, bufC, pas, pad_, a3s, a3d, NN, 448, 1);
    agg_kernel<32, 1, false, true><<<wb3, 256>>>(bufC, pas, pad_, b3, out, nullptr, nullptr);
}

// round 8
// speedup vs baseline: 1.4574x; 1.0217x over previous
#include <cuda_runtime.h>
#include <cuda_bf16.h>
#include <cstdint>

#define NN 50000
#define EE 800000
#define ET (EE + NN)          // edges + self loops
#define F12 448               // 7 heads * 64 ch
#define F3  32

// ---------------- scratch (static device globals; no allocation allowed) ----
__device__ __align__(128) float g_bufA[(size_t)NN * F12];  // GEMM output h (fp32)
__device__ __align__(128) float g_bufC[(size_t)NN * F3];   // layer-3 h
__device__ __align__(128) __nv_bfloat16 g_xh[(size_t)NN * 256], g_xl[(size_t)NN * 256];
__device__ __align__(128) __nv_bfloat16 g_ah[(size_t)NN * F12], g_al[(size_t)NN * F12];
__device__ float g_as[NN * 7];
__device__ float g_ad[NN * 7];
__device__ int g_cnt[NN];
__device__ int g_off[NN + 1];
__device__ int g_cur[NN];
__device__ int g_esrc[ET];
// transposed + bf16-split weights: WT[n*K + k] = W[k*N + n]
__device__ __align__(128) __nv_bfloat16 g_wt1h[448 * 256], g_wt1l[448 * 256];
__device__ __align__(128) __nv_bfloat16 g_wt2h[448 * 448], g_wt2l[448 * 448];
__device__ __align__(128) __nv_bfloat16 g_wt3h[32 * 448],  g_wt3l[32 * 448];

// ---------------- CSR build ------------------------------------------------
__global__ void zero_cnt_kernel() {
    int i = blockIdx.x * blockDim.x + threadIdx.x;
    if (i < NN) g_cnt[i] = 0;
}
__global__ void hist_kernel(const int* __restrict__ ei) {
    int e = blockIdx.x * blockDim.x + threadIdx.x;
    if (e >= ET) return;
    int dst = (e < EE) ? ei[EE + e] : (e - EE);
    atomicAdd(&g_cnt[dst], 1);
}
__global__ void scan_kernel() {
    __shared__ int sh[1024];
    __shared__ int carry_s;
    int tid = threadIdx.x;
    if (tid == 0) carry_s = 0;
    __syncthreads();
    for (int base = 0; base < NN; base += 1024) {
        int i = base + tid;
        int v = (i < NN) ? g_cnt[i] : 0;
        sh[tid] = v;
        __syncthreads();
        for (int off = 1; off < 1024; off <<= 1) {
            int t = (tid >= off) ? sh[tid - off] : 0;
            __syncthreads();
            sh[tid] += t;
            __syncthreads();
        }
        int incl = sh[tid];
        int c = carry_s;
        if (i < NN) { g_off[i] = c + incl - v; g_cur[i] = c + incl - v; }
        __syncthreads();
        if (tid == 1023) carry_s = c + sh[1023];
        __syncthreads();
    }
    if (tid == 0) g_off[NN] = carry_s;
}
__global__ void scatter_kernel(const int* __restrict__ ei) {
    int e = blockIdx.x * blockDim.x + threadIdx.x;
    if (e >= ET) return;
    int src, dst;
    if (e < EE) { src = ei[e]; dst = ei[EE + e]; }
    else        { src = e - EE; dst = src; }
    int p = atomicAdd(&g_cur[dst], 1);
    g_esrc[p] = src;
}

// ---------------- W transpose + bf16 split ---------------------------------
__global__ void convW_kernel(const float* __restrict__ W, __nv_bfloat16* __restrict__ Th,
                             __nv_bfloat16* __restrict__ Tl, int K, int Ncol) {
    int idx = blockIdx.x * blockDim.x + threadIdx.x;
    if (idx >= K * Ncol) return;
    int n = idx / K, k = idx % K;
    float v = W[(size_t)k * Ncol + n];
    __nv_bfloat16 hh = __float2bfloat16(v);
    Th[idx] = hh;
    Tl[idx] = __float2bfloat16(v - __bfloat162float(hh));
}

// ---------------- x split (fp32 -> bf16 hi/lo) -----------------------------
__global__ void splitX_kernel(const float* __restrict__ x, __nv_bfloat16* __restrict__ xh,
                              __nv_bfloat16* __restrict__ xl, int total4) {
    int i = blockIdx.x * blockDim.x + threadIdx.x;
    if (i >= total4) return;
    float4 v = *(const float4*)(x + (size_t)i * 4);
    float f[4] = {v.x, v.y, v.z, v.w};
    __nv_bfloat16 h[4], l[4];
#pragma unroll
    for (int j = 0; j < 4; j++) {
        h[j] = __float2bfloat16(f[j]);
        l[j] = __float2bfloat16(f[j] - __bfloat162float(h[j]));
    }
    *(uint2*)(xh + (size_t)i * 4) = *(uint2*)h;
    *(uint2*)(xl + (size_t)i * 4) = *(uint2*)l;
}

// ---------------- mma / ldmatrix / cp.async helpers ------------------------
__device__ __forceinline__ void mma16816(float* c, const uint32_t* a, const uint32_t* b) {
    asm volatile(
        "mma.sync.aligned.m16n8k16.row.col.f32.bf16.bf16.f32 "
        "{%0,%1,%2,%3}, {%4,%5,%6,%7}, {%8,%9}, {%0,%1,%2,%3};"
        : "+f"(c[0]), "+f"(c[1]), "+f"(c[2]), "+f"(c[3])
        : "r"(a[0]), "r"(a[1]), "r"(a[2]), "r"(a[3]), "r"(b[0]), "r"(b[1]));
}
__device__ __forceinline__ void ldsm4(uint32_t& r0, uint32_t& r1, uint32_t& r2, uint32_t& r3,
                                      uint32_t addr) {
    asm volatile("ldmatrix.sync.aligned.m8n8.x4.shared.b16 {%0,%1,%2,%3}, [%4];"
        : "=r"(r0), "=r"(r1), "=r"(r2), "=r"(r3) : "r"(addr));
}
__device__ __forceinline__ uint32_t smem_u32(const void* p) {
    uint32_t a;
    asm("{ .reg .u64 t; cvta.to.shared.u64 t, %1; cvt.u32.u64 %0, t; }" : "=r"(a) : "l"(p));
    return a;
}
__device__ __forceinline__ void cp16(uint32_t dst, const void* src) {
    asm volatile("cp.async.cg.shared.global [%0], [%1], 16;" :: "r"(dst), "l"(src));
}
#define CP_COMMIT() asm volatile("cp.async.commit_group;" ::: "memory")
#define CP_WAIT1()  asm volatile("cp.async.wait_group 1;" ::: "memory")
#define CP_WAIT0()  asm volatile("cp.async.wait_group 0;" ::: "memory")

// ---------------- bf16-split GEMM, cp.async 2-stage pipeline ---------------
// Block: 256 thr = 8 warps (4 in M x 2 in N). BM=128, BN=CH (one head), BK=64.
// C = (Ah+Al) @ (Bh+Bl)^T via 3 terms: AhBh + AhBl + AlBh.
template<int CH>
__global__ void __launch_bounds__(256)
gemm_gat(const __nv_bfloat16* __restrict__ Agh, const __nv_bfloat16* __restrict__ Agl,
         const __nv_bfloat16* __restrict__ BTh, const __nv_bfloat16* __restrict__ BTl,
         float* __restrict__ C, float* __restrict__ as_o, float* __restrict__ ad_o,
         const float* __restrict__ a_src, const float* __restrict__ a_dst,
         int M, int K, int NH) {
    constexpr int SP = 72;                 // smem row stride in halves (pad)
    constexpr int CHW = CH / 2;            // cols per N-warp
    constexpr int NT = CH / 16;            // 8-wide n-tiles per warp
    constexpr int ASZ = 128 * SP;          // halves
    constexpr int BSZ = CH * SP;
    constexpr int STAGE = 2 * ASZ + 2 * BSZ;   // halves per stage
    extern __shared__ char smem[];
    __nv_bfloat16* sm = (__nv_bfloat16*)smem;
    float* asbuf = (float*)(sm + 2 * STAGE);   // [128][2]
    float* adbuf = asbuf + 128 * 2;

    const int tid = threadIdx.x, wid = tid >> 5, lane = tid & 31;
    const int wm = wid & 3, wn = wid >> 2;
    const int gid = lane >> 2, tig = lane & 3;
    const int bm = blockIdx.y * 128;
    const int h = blockIdx.x;

    const __nv_bfloat16* bh = BTh + (size_t)h * CH * K;
    const __nv_bfloat16* bl = BTl + (size_t)h * CH * K;

    const uint32_t sb0 = smem_u32(sm);
    // per-thread load indices (constant across chunks)
    const int lr = tid >> 3, lt8 = tid & 7;  // A/B tile coords, iter stride 256 -> +32 rows
    // ldmatrix per-lane offsets (halves, relative to stage base)
    const int aoff = (wm * 32 + (lane & 15)) * SP + ((lane >> 4) << 3);
    const int boff = (wn * CHW + (lane & 7) + ((lane & 16) ? 8 : 0)) * SP + ((lane & 8) ? 8 : 0);

    float c[2][NT][4];
#pragma unroll
    for (int i = 0; i < 2; i++)
#pragma unroll
        for (int j = 0; j < NT; j++)
#pragma unroll
            for (int q = 0; q < 4; q++) c[i][j][q] = 0.f;

    const int nch = K >> 6;

    // stage loader: issue cp.asyncs for chunk ch into stage st
    auto load_stage = [&](int st, int ch) {
        const int k0 = ch << 6;
        const uint32_t base = sb0 + (uint32_t)st * STAGE * 2;
        const uint32_t aHi = base, aLo = base + ASZ * 2;
        const uint32_t bHi = base + 2 * ASZ * 2, bLo = bHi + BSZ * 2;
#pragma unroll
        for (int it = 0; it < 4; it++) {
            int r = lr + it * 32;
            size_t gidx = (size_t)min(bm + r, M - 1) * K + k0 + lt8 * 8;
            uint32_t off = (uint32_t)(r * SP + lt8 * 8) * 2;
            cp16(aHi + off, Agh + gidx);
            cp16(aLo + off, Agl + gidx);
        }
#pragma unroll
        for (int it = 0; it < CH * 8 / 256; it++) {
            int n = lr + it * 32;
            size_t gidx = (size_t)n * K + k0 + lt8 * 8;
            uint32_t off = (uint32_t)(n * SP + lt8 * 8) * 2;
            cp16(bHi + off, bh + gidx);
            cp16(bLo + off, bl + gidx);
        }
    };

    load_stage(0, 0);
    CP_COMMIT();

    for (int ch = 0; ch < nch; ch++) {
        if (ch + 1 < nch) { load_stage((ch + 1) & 1, ch + 1); CP_COMMIT(); CP_WAIT1(); }
        else              { CP_WAIT0(); }
        __syncthreads();
        const uint32_t base = sb0 + (uint32_t)(ch & 1) * STAGE * 2;
        const uint32_t sAhi = base, sAlo = base + ASZ * 2;
        const uint32_t sBhi = base + 2 * ASZ * 2, sBlo = sBhi + BSZ * 2;
#pragma unroll
        for (int kk = 0; kk < 4; kk++) {
            const int kb = kk * 16;
            uint32_t ah[2][4], al[2][4];
#pragma unroll
            for (int mt = 0; mt < 2; mt++) {
                uint32_t off = (uint32_t)(aoff + mt * 16 * SP + kb) * 2;
                ldsm4(ah[mt][0], ah[mt][1], ah[mt][2], ah[mt][3], sAhi + off);
                ldsm4(al[mt][0], al[mt][1], al[mt][2], al[mt][3], sAlo + off);
            }
            uint32_t bhf[NT][2], blf[NT][2];
#pragma unroll
            for (int tp = 0; tp < NT / 2; tp++) {
                uint32_t off = (uint32_t)(boff + tp * 16 * SP + kb) * 2;
                ldsm4(bhf[2 * tp][0], bhf[2 * tp][1], bhf[2 * tp + 1][0], bhf[2 * tp + 1][1], sBhi + off);
                ldsm4(blf[2 * tp][0], blf[2 * tp][1], blf[2 * tp + 1][0], blf[2 * tp + 1][1], sBlo + off);
            }
#pragma unroll
            for (int mt = 0; mt < 2; mt++)
#pragma unroll
                for (int nt = 0; nt < NT; nt++) {
                    mma16816(c[mt][nt], ah[mt], bhf[nt]);
                    mma16816(c[mt][nt], ah[mt], blf[nt]);
                    mma16816(c[mt][nt], al[mt], bhf[nt]);
                }
        }
        __syncthreads();
    }

    // ---- epilogue: write C + fused alpha dots ----
    float pa[2][2], pd[2][2];
#pragma unroll
    for (int mt = 0; mt < 2; mt++)
#pragma unroll
        for (int r2 = 0; r2 < 2; r2++) { pa[mt][r2] = 0.f; pd[mt][r2] = 0.f; }
#pragma unroll
    for (int mt = 0; mt < 2; mt++) {
#pragma unroll
        for (int nt = 0; nt < NT; nt++) {
            int col = wn * CHW + nt * 8 + tig * 2;
            int row0 = bm + wm * 32 + mt * 16 + gid;
            float s0 = a_src[h * CH + col], s1 = a_src[h * CH + col + 1];
            float d0 = a_dst[h * CH + col], d1 = a_dst[h * CH + col + 1];
            pa[mt][0] += c[mt][nt][0] * s0 + c[mt][nt][1] * s1;
            pd[mt][0] += c[mt][nt][0] * d0 + c[mt][nt][1] * d1;
            pa[mt][1] += c[mt][nt][2] * s0 + c[mt][nt][3] * s1;
            pd[mt][1] += c[mt][nt][2] * d0 + c[mt][nt][3] * d1;
            if (row0 < M)
                *(float2*)&C[(size_t)row0 * NH * CH + h * CH + col] =
                    make_float2(c[mt][nt][0], c[mt][nt][1]);
            if (row0 + 8 < M)
                *(float2*)&C[(size_t)(row0 + 8) * NH * CH + h * CH + col] =
                    make_float2(c[mt][nt][2], c[mt][nt][3]);
        }
    }
#pragma unroll
    for (int mt = 0; mt < 2; mt++)
#pragma unroll
        for (int r2 = 0; r2 < 2; r2++) {
#pragma unroll
            for (int o = 1; o < 4; o <<= 1) {
                pa[mt][r2] += __shfl_xor_sync(0xffffffffu, pa[mt][r2], o);
                pd[mt][r2] += __shfl_xor_sync(0xffffffffu, pd[mt][r2], o);
            }
            if (tig == 0) {
                int rl = wm * 32 + mt * 16 + r2 * 8 + gid;
                asbuf[rl * 2 + wn] = pa[mt][r2];
                adbuf[rl * 2 + wn] = pd[mt][r2];
            }
        }
    __syncthreads();
    if (tid < 128) {
        int row = bm + tid;
        if (row < M) {
            as_o[row * NH + h] = asbuf[tid * 2] + asbuf[tid * 2 + 1];
            ad_o[row * NH + h] = adbuf[tid * 2] + adbuf[tid * 2 + 1];
        }
    }
}

// ---------------- gather-side online-softmax aggregation (C=64) ------------
// one warp per (dst,head); lane owns channels 2*lane, 2*lane+1 (float2 loads)
// lazy rescale: e is warp-uniform; rescale only on new running max.
template<int NH, bool RELU>
__global__ void agg64_kernel(const float* __restrict__ h, const float* __restrict__ as,
                             const float* __restrict__ ad, const float* __restrict__ bias,
                             __nv_bfloat16* __restrict__ oh, __nv_bfloat16* __restrict__ ol) {
    int gw = (blockIdx.x * blockDim.x + threadIdx.x) >> 5;
    int lane = threadIdx.x & 31;
    if (gw >= NN * NH) return;
    int n = gw / NH, hh = gw % NH;
    int beg = g_off[n], end = g_off[n + 1];
    float adn = ad[gw];
    float ax = 0.f, ay = 0.f;
    float m = -1e30f, dsum = 0.f;
    for (int i = beg; i < end; i++) {
        int s = g_esrc[i];
        float e = as[s * NH + hh] + adn;
        e = e > 0.f ? e : 0.2f * e;                 // leaky relu
        float2 hv = __ldg((const float2*)(h + (size_t)s * NH * 64 + hh * 64) + lane);
        if (e <= m) {                               // warp-uniform branch
            float w = __expf(e - m);
            dsum += w;
            ax += w * hv.x; ay += w * hv.y;
        } else {
            float sc = __expf(m - e);
            dsum = dsum * sc + 1.f;
            ax = ax * sc + hv.x; ay = ay * sc + hv.y;
            m = e;
        }
    }
    float inv = 1.f / (dsum + 1e-16f);
    float r0 = ax * inv + bias[hh * 64 + 2 * lane];
    float r1 = ay * inv + bias[hh * 64 + 2 * lane + 1];
    if (RELU) { r0 = fmaxf(r0, 0.f); r1 = fmaxf(r1, 0.f); }
    size_t idx = (size_t)n * NH * 64 + hh * 64 + 2 * lane;
    __nv_bfloat16 h0 = __float2bfloat16(r0), h1 = __float2bfloat16(r1);
    __nv_bfloat162 ph(h0, h1);
    __nv_bfloat162 pl(__float2bfloat16(r0 - __bfloat162float(h0)),
                      __float2bfloat16(r1 - __bfloat162float(h1)));
    *(uint32_t*)(oh + idx) = *(uint32_t*)&ph;
    *(uint32_t*)(ol + idx) = *(uint32_t*)&pl;
}

// ---------------- layer-3 aggregation + fused log_softmax (C=32, NH=1) ----
__global__ void agg32_kernel(const float* __restrict__ h, const float* __restrict__ as,
                             const float* __restrict__ ad, const float* __restrict__ bias,
                             float* __restrict__ out) {
    int gw = (blockIdx.x * blockDim.x + threadIdx.x) >> 5;
    int lane = threadIdx.x & 31;
    if (gw >= NN) return;
    int n = gw;
    int beg = g_off[n], end = g_off[n + 1];
    float adn = ad[n];
    float acc = 0.f, m = -1e30f, dsum = 0.f;
    for (int i = beg; i < end; i++) {
        int s = g_esrc[i];
        float e = as[s] + adn;
        e = e > 0.f ? e : 0.2f * e;
        float hv = __ldg(h + (size_t)s * 32 + lane);
        if (e <= m) {
            float w = __expf(e - m);
            dsum += w; acc += w * hv;
        } else {
            float sc = __expf(m - e);
            dsum = dsum * sc + 1.f;
            acc = acc * sc + hv;
            m = e;
        }
    }
    float inv = 1.f / (dsum + 1e-16f);
    float r = acc * inv + bias[lane];
    float mx = r;
#pragma unroll
    for (int o = 16; o; o >>= 1) mx = fmaxf(mx, __shfl_xor_sync(0xffffffffu, mx, o));
    float ex = __expf(r - mx);
    float sm = ex;
#pragma unroll
    for (int o = 16; o; o >>= 1) sm += __shfl_xor_sync(0xffffffffu, sm, o);
    out[(size_t)n * 32 + lane] = r - mx - logf(sm);
}

// ---------------- launch ---------------------------------------------------
extern "C" void kernel_launch(void* const* d_in, const int* in_sizes, int n_in,
                              void* d_out, int out_size) {
    const float* x   = (const float*)d_in[0];
    const int*   ei  = (const int*)d_in[1];
    const float* W1  = (const float*)d_in[2];
    const float* a1s = (const float*)d_in[3];
    const float* a1d = (const float*)d_in[4];
    const float* b1  = (const float*)d_in[5];
    const float* W2  = (const float*)d_in[6];
    const float* a2s = (const float*)d_in[7];
    const float* a2d = (const float*)d_in[8];
    const float* b2  = (const float*)d_in[9];
    const float* W3  = (const float*)d_in[10];
    const float* a3s = (const float*)d_in[11];
    const float* a3d = (const float*)d_in[12];
    const float* b3  = (const float*)d_in[13];
    float* out = (float*)d_out;

    float *bufA, *bufC, *pas, *pad_;
    __nv_bfloat16 *xh, *xl, *ah, *al;
    __nv_bfloat16 *wt1h, *wt1l, *wt2h, *wt2l, *wt3h, *wt3l;
    cudaGetSymbolAddress((void**)&bufA, g_bufA);
    cudaGetSymbolAddress((void**)&bufC, g_bufC);
    cudaGetSymbolAddress((void**)&pas, g_as);
    cudaGetSymbolAddress((void**)&pad_, g_ad);
    cudaGetSymbolAddress((void**)&xh, g_xh);
    cudaGetSymbolAddress((void**)&xl, g_xl);
    cudaGetSymbolAddress((void**)&ah, g_ah);
    cudaGetSymbolAddress((void**)&al, g_al);
    cudaGetSymbolAddress((void**)&wt1h, g_wt1h);
    cudaGetSymbolAddress((void**)&wt1l, g_wt1l);
    cudaGetSymbolAddress((void**)&wt2h, g_wt2h);
    cudaGetSymbolAddress((void**)&wt2l, g_wt2l);
    cudaGetSymbolAddress((void**)&wt3h, g_wt3h);
    cudaGetSymbolAddress((void**)&wt3l, g_wt3l);

    // smem: 2 stages of (A hi/lo 128*72 + B hi/lo CH*72) halves + 512 floats
    const int SMEM64 = 2 * (2 * 128 * 72 + 2 * 64 * 72) * 2 + 2 * 128 * 2 * 4;  // 112640
    const int SMEM32 = 2 * (2 * 128 * 72 + 2 * 32 * 72) * 2 + 2 * 128 * 2 * 4;  // 94208
    cudaFuncSetAttribute(gemm_gat<64>, cudaFuncAttributeMaxDynamicSharedMemorySize, SMEM64);
    cudaFuncSetAttribute(gemm_gat<32>, cudaFuncAttributeMaxDynamicSharedMemorySize, SMEM32);

    // ---- CSR by destination ----
    zero_cnt_kernel<<<(NN + 255) / 256, 256>>>();
    hist_kernel<<<(ET + 255) / 256, 256>>>(ei);
    scan_kernel<<<1, 1024>>>();
    scatter_kernel<<<(ET + 255) / 256, 256>>>(ei);

    // ---- weight transpose + split, x split ----
    convW_kernel<<<(448 * 256 + 255) / 256, 256>>>(W1, wt1h, wt1l, 256, 448);
    convW_kernel<<<(448 * 448 + 255) / 256, 256>>>(W2, wt2h, wt2l, 448, 448);
    convW_kernel<<<(32 * 448 + 255) / 256, 256>>>(W3, wt3h, wt3l, 448, 32);
    splitX_kernel<<<(NN * 256 / 4 + 255) / 256, 256>>>(x, xh, xl, NN * 256 / 4);

    const int MB = (NN + 127) / 128;              // 391
    const int wb12 = (NN * 7 * 32 + 255) / 256;
    const int wb3  = (NN * 1 * 32 + 255) / 256;

    // ---- layer 1 ----
    gemm_gat<64><<<dim3(7, MB), 256, SMEM64>>>(xh, xl, wt1h, wt1l, bufA, pas, pad_, a1s, a1d, NN, 256, 7);
    agg64_kernel<7, true><<<wb12, 256>>>(bufA, pas, pad_, b1, ah, al);

    // ---- layer 2 ----
    gemm_gat<64><<<dim3(7, MB), 256, SMEM64>>>(ah, al, wt2h, wt2l, bufA, pas, pad_, a2s, a2d, NN, 448, 7);
    agg64_kernel<7, true><<<wb12, 256>>>(bufA, pas, pad_, b2, ah, al);

    // ---- layer 3 (+ fused log_softmax) ----
    gemm_gat<32><<<dim3(1, MB), 256, SMEM32>>>(ah, al, wt3h, wt3l, bufC, pas, pad_, a3s, a3d, NN, 448, 1);
    agg32_kernel<<<wb3, 256>>>(bufC, pas, pad_, b3, out);
}

// round 10
// speedup vs baseline: 1.4778x; 1.0140x over previous
#include <cuda_runtime.h>
#include <cuda_bf16.h>
#include <cstdint>

#define NN 50000
#define EE 800000
#define ET (EE + NN)          // edges + self loops
#define F12 448               // 7 heads * 64 ch
#define F3  32

// ---------------- scratch (static device globals; no allocation allowed) ----
__device__ __align__(128) float g_bufA[(size_t)NN * F12];  // GEMM output h (fp32)
__device__ __align__(128) float g_bufC[(size_t)NN * F3];   // layer-3 h
__device__ __align__(128) float g_xt[(size_t)NN * 256];    // x, tf32-rounded
__device__ __align__(128) float g_at[(size_t)NN * F12];    // agg out, tf32-rounded
__device__ float g_as[NN * 7];
__device__ float g_ad[NN * 7];
__device__ int g_cnt[NN];
__device__ int g_off[NN + 1];
__device__ int g_cur[NN];
__device__ int g_esrc[ET];
// transposed tf32-rounded weights: WT[n*K + k] = W[k*N + n]
__device__ __align__(128) float g_wt1[448 * 256];
__device__ __align__(128) float g_wt2[448 * 448];
__device__ __align__(128) float g_wt3[32 * 448];

// ---------------- helpers --------------------------------------------------
__device__ __forceinline__ float tf32r(float v) {
    uint32_t t;
    asm("cvt.rna.tf32.f32 %0, %1;" : "=r"(t) : "f"(v));
    return __uint_as_float(t);
}
__device__ __forceinline__ uint32_t smem_u32(const void* p) {
    uint32_t a;
    asm("{ .reg .u64 t; cvta.to.shared.u64 t, %1; cvt.u32.u64 %0, t; }" : "=r"(a) : "l"(p));
    return a;
}
__device__ __forceinline__ void cp16(uint32_t dst, const void* src) {
    asm volatile("cp.async.cg.shared.global [%0], [%1], 16;" :: "r"(dst), "l"(src));
}
#define CP_COMMIT() asm volatile("cp.async.commit_group;" ::: "memory")
#define CP_WAIT1()  asm volatile("cp.async.wait_group 1;" ::: "memory")
#define CP_WAIT0()  asm volatile("cp.async.wait_group 0;" ::: "memory")

__device__ __forceinline__ void mma_tf32(float* c, const uint32_t* a, const uint32_t* b) {
    asm volatile(
        "mma.sync.aligned.m16n8k8.row.col.f32.tf32.tf32.f32 "
        "{%0,%1,%2,%3}, {%4,%5,%6,%7}, {%8,%9}, {%0,%1,%2,%3};"
        : "+f"(c[0]), "+f"(c[1]), "+f"(c[2]), "+f"(c[3])
        : "r"(a[0]), "r"(a[1]), "r"(a[2]), "r"(a[3]), "r"(b[0]), "r"(b[1]));
}

// ---------------- CSR build ------------------------------------------------
__global__ void zero_cnt_kernel() {
    int i = blockIdx.x * blockDim.x + threadIdx.x;
    if (i < NN) g_cnt[i] = 0;
}
__global__ void hist_kernel(const int* __restrict__ ei) {
    int e = blockIdx.x * blockDim.x + threadIdx.x;
    if (e >= ET) return;
    int dst = (e < EE) ? ei[EE + e] : (e - EE);
    atomicAdd(&g_cnt[dst], 1);
}
__global__ void scan_kernel() {
    __shared__ int sh[1024];
    __shared__ int carry_s;
    int tid = threadIdx.x;
    if (tid == 0) carry_s = 0;
    __syncthreads();
    for (int base = 0; base < NN; base += 1024) {
        int i = base + tid;
        int v = (i < NN) ? g_cnt[i] : 0;
        sh[tid] = v;
        __syncthreads();
        for (int off = 1; off < 1024; off <<= 1) {
            int t = (tid >= off) ? sh[tid - off] : 0;
            __syncthreads();
            sh[tid] += t;
            __syncthreads();
        }
        int incl = sh[tid];
        int c = carry_s;
        if (i < NN) { g_off[i] = c + incl - v; g_cur[i] = c + incl - v; }
        __syncthreads();
        if (tid == 1023) carry_s = c + sh[1023];
        __syncthreads();
    }
    if (tid == 0) g_off[NN] = carry_s;
}
__global__ void scatter_kernel(const int* __restrict__ ei) {
    int e = blockIdx.x * blockDim.x + threadIdx.x;
    if (e >= ET) return;
    int src, dst;
    if (e < EE) { src = ei[e]; dst = ei[EE + e]; }
    else        { src = e - EE; dst = src; }
    int p = atomicAdd(&g_cur[dst], 1);
    g_esrc[p] = src;
}

// ---------------- W transpose + tf32 round ---------------------------------
__global__ void convW_kernel(const float* __restrict__ W, float* __restrict__ T,
                             int K, int Ncol) {
    int idx = blockIdx.x * blockDim.x + threadIdx.x;
    if (idx >= K * Ncol) return;
    int n = idx / K, k = idx % K;
    T[idx] = tf32r(W[(size_t)k * Ncol + n]);
}

// ---------------- x tf32 round ---------------------------------------------
__global__ void convX_kernel(const float* __restrict__ x, float* __restrict__ xt, int total4) {
    int i = blockIdx.x * blockDim.x + threadIdx.x;
    if (i >= total4) return;
    float4 v = *(const float4*)(x + (size_t)i * 4);
    v.x = tf32r(v.x); v.y = tf32r(v.y); v.z = tf32r(v.z); v.w = tf32r(v.w);
    *(float4*)(xt + (size_t)i * 4) = v;
}

// ---------------- TF32 GEMM, cp.async 2-stage + fused alpha epilogue -------
// Block: 256 thr = 8 warps (4 in M x 2 in N). BM=128, BN=CH (one head), BK=64.
// C[M, NH*CH] head-block = A[M,K] @ WT^T.
template<int CH>
__global__ void __launch_bounds__(256)
gemm_gat(const float* __restrict__ Ag, const float* __restrict__ BT,
         float* __restrict__ C, float* __restrict__ as_o, float* __restrict__ ad_o,
         const float* __restrict__ a_src, const float* __restrict__ a_dst,
         int M, int K, int NH) {
    constexpr int SP = 68;                 // smem row stride in floats (pad)
    constexpr int CHW = CH / 2;            // cols per N-warp
    constexpr int NT = CH / 16;            // 8-wide n-tiles per warp
    constexpr int ASZ = 128 * SP;          // floats
    constexpr int BSZ = CH * SP;
    constexpr int STAGE = ASZ + BSZ;       // floats per stage
    extern __shared__ char smem[];
    float* sm = (float*)smem;
    float* asbuf = sm + 2 * STAGE;         // [128][2]
    float* adbuf = asbuf + 128 * 2;

    const int tid = threadIdx.x, wid = tid >> 5, lane = tid & 31;
    const int wm = wid & 3, wn = wid >> 2;
    const int gid = lane >> 2, tig = lane & 3;
    const int bm = blockIdx.y * 128;
    const int h = blockIdx.x;

    const float* bsrc = BT + (size_t)h * CH * K;
    const uint32_t sb0 = smem_u32(sm);
    const int lr = tid >> 4, lq = tid & 15;   // 16 cp16 units per 64-float row

    float c[2][NT][4];
#pragma unroll
    for (int i = 0; i < 2; i++)
#pragma unroll
        for (int j = 0; j < NT; j++)
#pragma unroll
            for (int q = 0; q < 4; q++) c[i][j][q] = 0.f;

    const int nch = K >> 6;

    auto load_stage = [&](int st, int ch) {
        const int k0 = ch << 6;
        const uint32_t aB = sb0 + (uint32_t)st * STAGE * 4;
        const uint32_t bB = aB + ASZ * 4;
#pragma unroll
        for (int it = 0; it < 8; it++) {         // A: 128 rows x 64 floats
            int r = lr + it * 16;
            size_t gidx = (size_t)min(bm + r, M - 1) * K + k0 + lq * 4;
            cp16(aB + (uint32_t)(r * SP + lq * 4) * 4, Ag + gidx);
        }
#pragma unroll
        for (int it = 0; it < CH / 16; it++) {   // B: CH rows x 64 floats
            int n = lr + it * 16;
            size_t gidx = (size_t)n * K + k0 + lq * 4;
            cp16(bB + (uint32_t)(n * SP + lq * 4) * 4, bsrc + gidx);
        }
    };

    load_stage(0, 0);
    CP_COMMIT();

    for (int ch = 0; ch < nch; ch++) {
        if (ch + 1 < nch) { load_stage((ch + 1) & 1, ch + 1); CP_COMMIT(); CP_WAIT1(); }
        else              { CP_WAIT0(); }
        __syncthreads();
        const float* As = sm + (ch & 1) * STAGE;
        const float* Bs = As + ASZ;
        const uint32_t* As32 = (const uint32_t*)As;
        const uint32_t* Bs32 = (const uint32_t*)Bs;
        const int ar0 = (wm * 32 + gid) * SP;       // mt=0 row gid
        const int bn0 = (wn * CHW + gid) * SP;
#pragma unroll
        for (int ks = 0; ks < 8; ks++) {
            const int kb = ks * 8 + tig;
            uint32_t a[2][4], b[NT][2];
#pragma unroll
            for (int mt = 0; mt < 2; mt++) {
                int r = ar0 + mt * 16 * SP + kb;
                a[mt][0] = As32[r];
                a[mt][1] = As32[r + 8 * SP];
                a[mt][2] = As32[r + 4];
                a[mt][3] = As32[r + 8 * SP + 4];
            }
#pragma unroll
            for (int nt = 0; nt < NT; nt++) {
                int n = bn0 + nt * 8 * SP + kb;
                b[nt][0] = Bs32[n];
                b[nt][1] = Bs32[n + 4];
            }
#pragma unroll
            for (int mt = 0; mt < 2; mt++)
#pragma unroll
                for (int nt = 0; nt < NT; nt++)
                    mma_tf32(c[mt][nt], a[mt], b[nt]);
        }
        __syncthreads();
    }

    // ---- epilogue: write C + fused alpha dots ----
    float pa[2][2], pd[2][2];
#pragma unroll
    for (int mt = 0; mt < 2; mt++)
#pragma unroll
        for (int r2 = 0; r2 < 2; r2++) { pa[mt][r2] = 0.f; pd[mt][r2] = 0.f; }
#pragma unroll
    for (int mt = 0; mt < 2; mt++) {
#pragma unroll
        for (int nt = 0; nt < NT; nt++) {
            int col = wn * CHW + nt * 8 + tig * 2;
            int row0 = bm + wm * 32 + mt * 16 + gid;
            float s0 = a_src[h * CH + col], s1 = a_src[h * CH + col + 1];
            float d0 = a_dst[h * CH + col], d1 = a_dst[h * CH + col + 1];
            pa[mt][0] += c[mt][nt][0] * s0 + c[mt][nt][1] * s1;
            pd[mt][0] += c[mt][nt][0] * d0 + c[mt][nt][1] * d1;
            pa[mt][1] += c[mt][nt][2] * s0 + c[mt][nt][3] * s1;
            pd[mt][1] += c[mt][nt][2] * d0 + c[mt][nt][3] * d1;
            if (row0 < M)
                *(float2*)&C[(size_t)row0 * NH * CH + h * CH + col] =
                    make_float2(c[mt][nt][0], c[mt][nt][1]);
            if (row0 + 8 < M)
                *(float2*)&C[(size_t)(row0 + 8) * NH * CH + h * CH + col] =
                    make_float2(c[mt][nt][2], c[mt][nt][3]);
        }
    }
#pragma unroll
    for (int mt = 0; mt < 2; mt++)
#pragma unroll
        for (int r2 = 0; r2 < 2; r2++) {
#pragma unroll
            for (int o = 1; o < 4; o <<= 1) {
                pa[mt][r2] += __shfl_xor_sync(0xffffffffu, pa[mt][r2], o);
                pd[mt][r2] += __shfl_xor_sync(0xffffffffu, pd[mt][r2], o);
            }
            if (tig == 0) {
                int rl = wm * 32 + mt * 16 + r2 * 8 + gid;
                asbuf[rl * 2 + wn] = pa[mt][r2];
                adbuf[rl * 2 + wn] = pd[mt][r2];
            }
        }
    __syncthreads();
    if (tid < 128) {
        int row = bm + tid;
        if (row < M) {
            as_o[row * NH + h] = asbuf[tid * 2] + asbuf[tid * 2 + 1];
            ad_o[row * NH + h] = adbuf[tid * 2] + adbuf[tid * 2 + 1];
        }
    }
}

// ---------------- gather-side online-softmax aggregation (C=64) ------------
// one warp per (dst,head); lane owns channels 2*lane, 2*lane+1 (float2 loads)
// lazy rescale; output tf32-rounded fp32 (input of next GEMM)
template<int NH, bool RELU>
__global__ void agg64_kernel(const float* __restrict__ h, const float* __restrict__ as,
                             const float* __restrict__ ad, const float* __restrict__ bias,
                             float* __restrict__ oa) {
    int gw = (blockIdx.x * blockDim.x + threadIdx.x) >> 5;
    int lane = threadIdx.x & 31;
    if (gw >= NN * NH) return;
    int n = gw / NH, hh = gw % NH;
    int beg = g_off[n], end = g_off[n + 1];
    float adn = ad[gw];
    float ax = 0.f, ay = 0.f;
    float m = -1e30f, dsum = 0.f;
    for (int i = beg; i < end; i++) {
        int s = g_esrc[i];
        float e = as[s * NH + hh] + adn;
        e = e > 0.f ? e : 0.2f * e;                 // leaky relu
        float2 hv = __ldg((const float2*)(h + (size_t)s * NH * 64 + hh * 64) + lane);
        if (e <= m) {                               // warp-uniform branch
            float w = __expf(e - m);
            dsum += w;
            ax += w * hv.x; ay += w * hv.y;
        } else {
            float sc = __expf(m - e);
            dsum = dsum * sc + 1.f;
            ax = ax * sc + hv.x; ay = ay * sc + hv.y;
            m = e;
        }
    }
    float inv = 1.f / (dsum + 1e-16f);
    float r0 = ax * inv + bias[hh * 64 + 2 * lane];
    float r1 = ay * inv + bias[hh * 64 + 2 * lane + 1];
    if (RELU) { r0 = fmaxf(r0, 0.f); r1 = fmaxf(r1, 0.f); }
    size_t idx = (size_t)n * NH * 64 + hh * 64 + 2 * lane;
    *(float2*)(oa + idx) = make_float2(tf32r(r0), tf32r(r1));
}

// ---------------- layer-3 aggregation + fused log_softmax (C=32, NH=1) ----
__global__ void agg32_kernel(const float* __restrict__ h, const float* __restrict__ as,
                             const float* __restrict__ ad, const float* __restrict__ bias,
                             float* __restrict__ out) {
    int gw = (blockIdx.x * blockDim.x + threadIdx.x) >> 5;
    int lane = threadIdx.x & 31;
    if (gw >= NN) return;
    int n = gw;
    int beg = g_off[n], end = g_off[n + 1];
    float adn = ad[n];
    float acc = 0.f, m = -1e30f, dsum = 0.f;
    for (int i = beg; i < end; i++) {
        int s = g_esrc[i];
        float e = as[s] + adn;
        e = e > 0.f ? e : 0.2f * e;
        float hv = __ldg(h + (size_t)s * 32 + lane);
        if (e <= m) {
            float w = __expf(e - m);
            dsum += w; acc += w * hv;
        } else {
            float sc = __expf(m - e);
            dsum = dsum * sc + 1.f;
            acc = acc * sc + hv;
            m = e;
        }
    }
    float inv = 1.f / (dsum + 1e-16f);
    float r = acc * inv + bias[lane];
    float mx = r;
#pragma unroll
    for (int o = 16; o; o >>= 1) mx = fmaxf(mx, __shfl_xor_sync(0xffffffffu, mx, o));
    float ex = __expf(r - mx);
    float sm = ex;
#pragma unroll
    for (int o = 16; o; o >>= 1) sm += __shfl_xor_sync(0xffffffffu, sm, o);
    out[(size_t)n * 32 + lane] = r - mx - logf(sm);
}

// ---------------- launch ---------------------------------------------------
extern "C" void kernel_launch(void* const* d_in, const int* in_sizes, int n_in,
                              void* d_out, int out_size) {
    const float* x   = (const float*)d_in[0];
    const int*   ei  = (const int*)d_in[1];
    const float* W1  = (const float*)d_in[2];
    const float* a1s = (const float*)d_in[3];
    const float* a1d = (const float*)d_in[4];
    const float* b1  = (const float*)d_in[5];
    const float* W2  = (const float*)d_in[6];
    const float* a2s = (const float*)d_in[7];
    const float* a2d = (const float*)d_in[8];
    const float* b2  = (const float*)d_in[9];
    const float* W3  = (const float*)d_in[10];
    const float* a3s = (const float*)d_in[11];
    const float* a3d = (const float*)d_in[12];
    const float* b3  = (const float*)d_in[13];
    float* out = (float*)d_out;

    float *bufA, *bufC, *pas, *pad_, *xt, *at, *wt1, *wt2, *wt3;
    cudaGetSymbolAddress((void**)&bufA, g_bufA);
    cudaGetSymbolAddress((void**)&bufC, g_bufC);
    cudaGetSymbolAddress((void**)&pas, g_as);
    cudaGetSymbolAddress((void**)&pad_, g_ad);
    cudaGetSymbolAddress((void**)&xt, g_xt);
    cudaGetSymbolAddress((void**)&at, g_at);
    cudaGetSymbolAddress((void**)&wt1, g_wt1);
    cudaGetSymbolAddress((void**)&wt2, g_wt2);
    cudaGetSymbolAddress((void**)&wt3, g_wt3);

    // smem: 2 stages of (A 128*68 + B CH*68) floats + 512 floats for alpha
    const int SMEM64 = 2 * (128 * 68 + 64 * 68) * 4 + 2 * 128 * 2 * 4;  // 106496
    const int SMEM32 = 2 * (128 * 68 + 32 * 68) * 4 + 2 * 128 * 2 * 4;  //  89088
    cudaFuncSetAttribute(gemm_gat<64>, cudaFuncAttributeMaxDynamicSharedMemorySize, SMEM64);
    cudaFuncSetAttribute(gemm_gat<32>, cudaFuncAttributeMaxDynamicSharedMemorySize, SMEM32);

    const int MB = (NN + 127) / 128;              // 391
    const int wb12 = (NN * 7 * 32 + 255) / 256;
    const int wb3  = (NN * 1 * 32 + 255) / 256;

    // slots 0-2: gemm1 prerequisites; slot 3: gemm1 (ncu capture target)
    convX_kernel<<<(NN * 256 / 4 + 255) / 256, 256>>>(x, xt, NN * 256 / 4);
    convW_kernel<<<(448 * 256 + 255) / 256, 256>>>(W1, wt1, 256, 448);
    zero_cnt_kernel<<<(NN + 255) / 256, 256>>>();
    gemm_gat<64><<<dim3(7, MB), 256, SMEM64>>>(xt, wt1, bufA, pas, pad_, a1s, a1d, NN, 256, 7);

    // CSR build + remaining weight prep
    hist_kernel<<<(ET + 255) / 256, 256>>>(ei);
    scan_kernel<<<1, 1024>>>();
    scatter_kernel<<<(ET + 255) / 256, 256>>>(ei);
    convW_kernel<<<(448 * 448 + 255) / 256, 256>>>(W2, wt2, 448, 448);
    convW_kernel<<<(32 * 448 + 255) / 256, 256>>>(W3, wt3, 448, 32);

    // ---- layer 1 agg ----
    agg64_kernel<7, true><<<wb12, 256>>>(bufA, pas, pad_, b1, at);

    // ---- layer 2 ----
    gemm_gat<64><<<dim3(7, MB), 256, SMEM64>>>(at, wt2, bufA, pas, pad_, a2s, a2d, NN, 448, 7);
    agg64_kernel<7, true><<<wb12, 256>>>(bufA, pas, pad_, b2, at);

    // ---- layer 3 (+ fused log_softmax) ----
    gemm_gat<32><<<dim3(1, MB), 256, SMEM32>>>(at, wt3, bufC, pas, pad_, a3s, a3d, NN, 448, 1);
    agg32_kernel<<<wb3, 256>>>(bufC, pas, pad_, b3, out);
}